// round 15
// baseline (speedup 1.0000x reference)
#include <cuda_runtime.h>
#include <cuda_fp16.h>
#include <cstdint>

#define BN   128
#define DN   512
#define TN   512
#define NCTA 128
#define NTHR 512
#define HSZ  (BN * DN)   // 65536

// padded smem row strides (halves)
#define DKP  520    // 512-wide rows

// dynamic smem byte offsets (weights shrunk: only h/ap half of wA/wC resident)
#define OFF_WA   0                       // 32 x 520 halves = 33280 B
#define OFF_WC   33280                   // 33280 B
#define OFF_WIH  66560                   // 48 x 520 halves = 49920 B
#define OFF_R    116480                  // scratch union   = 43072 B
#define SMEM_TOTAL 159552

// Rbase internal layout:
//   s_tile (A/C K=512 act tile): 0 .. 16640
//   s_part (A/C reduction):      16640 .. 22784
//   s_e  (stage B):              39168 .. 40192
//   s_scr (stage B):             40192 .. 40256
//   stage D s_part:              0 .. 36864  (clobbers s_tile)

// ---------------- device scratch ----------------
__device__ __align__(16) __half d_xe[(size_t)BN * 32 * 32 * 256]; // x^T frag-tiled (einsum A)
__device__ __align__(16) __half d_xbm[(size_t)TN * BN * DN];      // [t][b][m]
__device__ __align__(16) float  d_LX[(size_t)TN * HSZ];           // xin @ attn_Wx^T  (fp32)
__device__ __align__(16) float  d_CX[(size_t)TN * HSZ];           // xin @ comb_Wx^T  (fp32)
__device__ __align__(16) __half d_wA[DN * 2 * DN];
__device__ __align__(16) __half d_wC[DN * 2 * DN];
__device__ __align__(16) __half d_wI[3 * DN * DN];
__device__ __align__(16) __half d_wH[3 * DN * DN];
__device__ __align__(16) __half d_wO[DN * DN];
__device__ __align__(16) float  d_elog[HSZ];
__device__ __align__(16) float  d_Spart[BN * 64];
__device__ __align__(16) __half d_g16t[HSZ];                   // g, TILED frag layout
__device__ __align__(16) __half d_ap16[HSZ];                   // [b][t']
__device__ __align__(16) __half d_h16[2][HSZ];                 // h row-major [b][j]
__device__ __align__(16) __half d_h16t[2][HSZ];                // h TILED frag layout
__device__ unsigned d_bar_count;
__device__ unsigned d_bar_sense;

// ---------------- merged prep kernel ----------------
__global__ void k_prep(const float* __restrict__ x,
                       const float* __restrict__ aW, const float* __restrict__ cW,
                       const float* __restrict__ wi, const float* __restrict__ wh,
                       const float* __restrict__ oW) {
    const int bx = blockIdx.x, tid = threadIdx.x;
    if (bx < 32768) {
        __shared__ float tile[32][33];
        int m0 = (bx & 15) * 32;
        int t0 = ((bx >> 4) & 15) * 32;
        int b  = bx >> 8;
        int tx = tid & 31;
        int ty = tid >> 5;
        #pragma unroll
        for (int r = 0; r < 32; r += 8)
            tile[ty + r][tx] = x[(size_t)b * DN * TN + (size_t)(m0 + ty + r) * TN + (t0 + tx)];
        __syncthreads();
        #pragma unroll
        for (int r = 0; r < 32; r += 8)
            d_xbm[(size_t)(t0 + ty + r) * HSZ + (size_t)b * DN + (m0 + tx)]
                = __float2half(tile[tx][ty + r]);
        {
            int sub = tid >> 6, v = tid & 63;
            int st = sub & 1, sm = sub >> 1;
            int L = v >> 1, p = v & 1;
            int g = L >> 2, tq = L & 3;
            int mb = sm * 16 + p * 8 + 2 * tq;
            int tb = st * 16 + g;
            __half2 h0 = __floats2half2_rn(tile[mb][tb],     tile[mb + 1][tb]);
            __half2 h1 = __floats2half2_rn(tile[mb][tb + 8], tile[mb + 1][tb + 8]);
            uint2 u;
            u.x = *(uint32_t*)&h0;
            u.y = *(uint32_t*)&h1;
            size_t base = (((size_t)b * 32 + (t0 >> 4) + st) * 32 + (m0 >> 4) + sm) * 256;
            *(uint2*)(d_xe + base + L * 8 + p * 4) = u;
        }
    } else if (bx < 35840) {
        int i = (bx - 32768) * 256 + tid;
        if (i < DN * 2 * DN) { d_wA[i] = __float2half(aW[i]); d_wC[i] = __float2half(cW[i]); }
        d_wI[i] = __float2half(wi[i]);
        d_wH[i] = __float2half(wh[i]);
        if (i < DN * DN) d_wO[i] = __float2half(oW[i]);
    } else {
        int i = (bx - 35840) * 256 + tid;
        if (i < HSZ) {
            d_h16[0][i]  = __float2half(0.0f);
            d_h16t[0][i] = __float2half(0.0f);
        }
        if (i == 0) { d_bar_count = 0u; d_bar_sense = 0u; }
    }
}

// ---------------- flat grid barrier (R7/R13-proven) ----------------
__device__ __forceinline__ void bar_arrive(unsigned& ep) {
    __syncthreads();
    ep += NCTA;
    if (threadIdx.x == 0) {
        __threadfence();
        unsigned a = atomicAdd(&d_bar_count, 1u) + 1u;
        if (a == ep) atomicExch(&d_bar_sense, ep);
    }
}
__device__ __forceinline__ void bar_wait(unsigned ep) {
    if (threadIdx.x == 0) {
        while (*(volatile unsigned*)&d_bar_sense < ep) { }
        __threadfence();
    }
    __syncthreads();
}

// ---------------- warp reduction ----------------
__device__ __forceinline__ float warpSum(float v) {
    #pragma unroll
    for (int o = 16; o; o >>= 1) v += __shfl_xor_sync(0xffffffffu, v, o);
    return v;
}

// ---------------- mma helpers ----------------
__device__ __forceinline__ void mma16816(float c[4], uint32_t a0, uint32_t a1,
                                         uint32_t a2, uint32_t a3,
                                         uint32_t b0, uint32_t b1) {
    asm volatile(
        "mma.sync.aligned.m16n8k16.row.col.f32.f16.f16.f32 "
        "{%0,%1,%2,%3}, {%4,%5,%6,%7}, {%8,%9}, {%0,%1,%2,%3};"
        : "+f"(c[0]), "+f"(c[1]), "+f"(c[2]), "+f"(c[3])
        : "r"(a0), "r"(a1), "r"(a2), "r"(a3), "r"(b0), "r"(b1));
}

__device__ __forceinline__ void ldAt(const __half* __restrict__ base, int bt, int kt,
                                     uint32_t A[4]) {
    const int lane = threadIdx.x & 31;
    uint4 v = *(const uint4*)(base + ((size_t)(bt * 32 + kt) << 8) + lane * 8);
    A[0] = v.x; A[1] = v.y; A[2] = v.z; A[3] = v.w;
}

__device__ __forceinline__ void ldB(const __half* __restrict__ W, int stride, int j0, int k,
                                    uint32_t Bf[2]) {
    const int lane = threadIdx.x & 31;
    const int g = lane >> 2, tig = lane & 3;
    const __half* p = W + (size_t)(j0 + g) * stride + k + tig * 2;
    Bf[0] = *(const uint32_t*)p;
    Bf[1] = *(const uint32_t*)(p + 8);
}

__device__ __forceinline__ void ldAs(const __half* s, int stridep, int k, uint32_t A[4]) {
    const int lane = threadIdx.x & 31;
    const int g = lane >> 2, tig = lane & 3;
    const __half* p0 = s + g * stridep + k + tig * 2;
    const __half* p1 = p0 + 8 * stridep;
    A[0] = *(const uint32_t*)p0;
    A[1] = *(const uint32_t*)p1;
    A[2] = *(const uint32_t*)(p0 + 8);
    A[3] = *(const uint32_t*)(p1 + 8);
}

__device__ __forceinline__ void ldBs(const __half* s, int stridep, int row0, int k,
                                     uint32_t Bf[2]) {
    const int lane = threadIdx.x & 31;
    const int g = lane >> 2, tig = lane & 3;
    const __half* p = s + (row0 + g) * stridep + k + tig * 2;
    Bf[0] = *(const uint32_t*)p;
    Bf[1] = *(const uint32_t*)(p + 8);
}

// ---------------- one-shot GEMM: LX/CX = xin(t) @ Wx^T ----------------
// grid (512 t, 4 jq, 2 mat), block 512. Per CTA: M=128 b, N=128 j, K=512.
__global__ void __launch_bounds__(512) k_lxcx() {
    __shared__ __half sx[128 * 136];      // 34816 B, +8 pad per row
    const int t = blockIdx.x, jq = blockIdx.y, mat = blockIdx.z;
    const int tid = threadIdx.x;
    const int warp = tid >> 5, lane = tid & 31;
    const int mt = warp & 7, nh = warp >> 3;
    const __half* W = mat ? d_wC : d_wA;  // [512 j][1024 k]; xin = cols 0..511
    float* OUT = mat ? d_CX : d_LX;
    float acc[8][4] = {};
    const __half* xsrc = d_xbm + (size_t)t * HSZ;
    for (int kb = 0; kb < 4; ++kb) {
        __syncthreads();
        #pragma unroll
        for (int i = 0; i < 4; ++i) {
            int u = tid + i * 512;            // 0..2047
            int row = u >> 4, cc = u & 15;    // 128 rows x 16 uint4
            *(uint4*)(sx + row * 136 + cc * 8)
                = *(const uint4*)(xsrc + (size_t)row * DN + kb * 128 + cc * 8);
        }
        __syncthreads();
        #pragma unroll 2
        for (int ks = 0; ks < 8; ++ks) {
            uint32_t A[4];
            ldAs(sx + mt * 16 * 136, 136, ks * 16, A);
            #pragma unroll
            for (int nb = 0; nb < 8; ++nb) {
                uint32_t Bf[2];
                int j0 = jq * 128 + nh * 64 + nb * 8;
                ldB(W, 2 * DN, j0, kb * 128 + ks * 16, Bf);
                mma16816(acc[nb], A[0], A[1], A[2], A[3], Bf[0], Bf[1]);
            }
        }
    }
    const int g = lane >> 2, tig = lane & 3;
    #pragma unroll
    for (int nb = 0; nb < 8; ++nb) {
        int j = jq * 128 + nh * 64 + nb * 8 + tig * 2;
        size_t r0 = ((size_t)t * BN + mt * 16 + g) * DN + j;
        *(float2*)(OUT + r0)          = make_float2(acc[nb][0], acc[nb][1]);
        *(float2*)(OUT + r0 + 8 * DN) = make_float2(acc[nb][2], acc[nb][3]);
    }
}

// ---------------- K=512 tile loader (all 512 threads) ----------------
__device__ __forceinline__ void load_k512(const __half* __restrict__ src, __half* s_tile,
                                          int b0) {
    const int tid = threadIdx.x;
    #pragma unroll
    for (int i = 0; i < 2; ++i) {
        int u = tid + i * NTHR;
        int row = u >> 6, cc = u & 63;
        *(uint4*)(s_tile + row * DKP + cc * 8)
            = *(const uint4*)(src + (size_t)(b0 + row) * DN + cc * 8);
    }
}

// ---------------- stages A / C compute (K=512 dyn half + precomputed partial) --
// mode 0: exp(cc + px + bias) -> d_elog + d_Spart. mode 1: relu -> TILED g16t.
__device__ __forceinline__ void mma_AC(
    const __half* wS, const float* __restrict__ px, const float* __restrict__ bias,
    int mode, __half* __restrict__ out16t, char* Rbase)
{
    const int c = blockIdx.x, tid = threadIdx.x;
    const int warp = tid >> 5, lane = tid & 31;
    const int b0 = (c >> 4) * 16, ng = c & 15;
    const int nt = warp & 3, kh = warp >> 2;
    __half* s_tile = (__half*)Rbase;               // 16 x 520
    float*  s_part = (float*)(Rbase + 16640);

    float cc[4] = {0.f, 0.f, 0.f, 0.f};
    const int k0 = kh * 128;
    #pragma unroll
    for (int k = 0; k < 128; k += 16) {
        uint32_t A[4], Bf[2];
        ldAs(s_tile, DKP, k0 + k, A);
        ldBs(wS, DKP, nt * 8, k0 + k, Bf);
        mma16816(cc, A[0], A[1], A[2], A[3], Bf[0], Bf[1]);
    }
    if (kh) {
        float* p = s_part + ((kh - 1) * 4 + nt) * 128 + lane * 4;
        p[0] = cc[0]; p[1] = cc[1]; p[2] = cc[2]; p[3] = cc[3];
    }
    __syncthreads();
    if (!kh) {
        #pragma unroll
        for (int q = 0; q < 3; ++q) {
            const float* p = s_part + (q * 4 + nt) * 128 + lane * 4;
            cc[0] += p[0]; cc[1] += p[1]; cc[2] += p[2]; cc[3] += p[3];
        }
        const int g = lane >> 2, tig = lane & 3;
        const int j = ng * 32 + nt * 8 + tig * 2;
        float2 px0 = *(const float2*)(px + (size_t)(b0 + g) * DN + j);
        float2 px1 = *(const float2*)(px + (size_t)(b0 + g + 8) * DN + j);
        const float bz0 = bias[j], bz1 = bias[j + 1];
        if (mode == 1) {
            float v0 = fmaxf(cc[0] + px0.x + bz0, 0.f), v1 = fmaxf(cc[1] + px0.y + bz1, 0.f);
            float v2 = fmaxf(cc[2] + px1.x + bz0, 0.f), v3 = fmaxf(cc[3] + px1.y + bz1, 0.f);
            const int kt = ng * 2 + (nt >> 1);
            __half2 h0 = __floats2half2_rn(v0, v1);
            __half2 h1 = __floats2half2_rn(v2, v3);
            uint2 u;
            u.x = *(uint32_t*)&h0;
            u.y = *(uint32_t*)&h1;
            *(uint2*)(out16t + ((size_t)((c >> 4) * 32 + kt) << 8) + lane * 8 + (nt & 1) * 4) = u;
        } else {
            float e0 = __expf(cc[0] + px0.x + bz0), e1 = __expf(cc[1] + px0.y + bz1);
            float e2 = __expf(cc[2] + px1.x + bz0), e3 = __expf(cc[3] + px1.y + bz1);
            *(float2*)(d_elog + (size_t)(b0 + g) * DN + j)     = make_float2(e0, e1);
            *(float2*)(d_elog + (size_t)(b0 + g + 8) * DN + j) = make_float2(e2, e3);
            float s01 = e0 + e1, s23 = e2 + e3;
            s01 += __shfl_xor_sync(0xffffffffu, s01, 1);
            s23 += __shfl_xor_sync(0xffffffffu, s23, 1);
            s01 += __shfl_xor_sync(0xffffffffu, s01, 2);
            s23 += __shfl_xor_sync(0xffffffffu, s23, 2);
            if (tig == 0) {
                d_Spart[(b0 + g) * 64 + ng * 4 + nt]     = s01;
                d_Spart[(b0 + g + 8) * 64 + ng * 4 + nt] = s23;
            }
        }
    }
}

// ---------------- stage B: tensor-core einsum, CTA = batch b (R13-proven) ----
__device__ __forceinline__ void stageB(char* Rbase, unsigned ep) {
    const int b = blockIdx.x, tid = threadIdx.x;
    const int warp = tid >> 5, lane = tid & 31;
    const int g = lane >> 2, tq = lane & 3;
    __half* s_e   = (__half*)(Rbase + 39168);
    float*  s_scr = (float*)(Rbase + 40192);
    const __half* xb = d_xe + ((size_t)b * 32 + warp * 2) * 32 * 256;

    uint4 p0[4], p1[4];
    #pragma unroll
    for (int i = 0; i < 4; ++i) {
        p0[i] = *(const uint4*)(xb + (size_t)i * 256 + lane * 8);
        p1[i] = *(const uint4*)(xb + (size_t)(32 + i) * 256 + lane * 8);
    }

    bar_wait(ep);   // logits/Spart now globally visible

    float part = d_Spart[b * 64 + (tid & 63)];
    s_e[tid] = __float2half(d_elog[(size_t)b * DN + tid]);
    float ws = warpSum(part);
    if (lane == 0) s_scr[warp] = ws;
    __syncthreads();
    const float inv = 1.0f / (s_scr[0] + s_scr[1]);

    float c0[4] = {0.f, 0.f, 0.f, 0.f};
    float c1[4] = {0.f, 0.f, 0.f, 0.f};
    #pragma unroll
    for (int k = 0; k < 4; ++k) {
        uint32_t e0 = *(const uint32_t*)(s_e + k * 16 + 2 * tq);
        uint32_t e1 = *(const uint32_t*)(s_e + k * 16 + 8 + 2 * tq);
        mma16816(c0, p0[k].x, p0[k].y, p0[k].z, p0[k].w, e0, e1);
        mma16816(c1, p1[k].x, p1[k].y, p1[k].z, p1[k].w, e0, e1);
    }
    #pragma unroll
    for (int k = 4; k < 32; ++k) {
        uint4 v0 = *(const uint4*)(xb + (size_t)k * 256 + lane * 8);
        uint4 v1 = *(const uint4*)(xb + (size_t)(32 + k) * 256 + lane * 8);
        uint32_t e0 = *(const uint32_t*)(s_e + k * 16 + 2 * tq);
        uint32_t e1 = *(const uint32_t*)(s_e + k * 16 + 8 + 2 * tq);
        mma16816(c0, v0.x, v0.y, v0.z, v0.w, e0, e1);
        mma16816(c1, v1.x, v1.y, v1.z, v1.w, e0, e1);
    }
    if (tq == 0) {
        int tp = warp * 32 + g;
        d_ap16[(size_t)b * DN + tp]      = __float2half(c0[0] * inv);
        d_ap16[(size_t)b * DN + tp + 8]  = __float2half(c0[2] * inv);
        d_ap16[(size_t)b * DN + tp + 16] = __float2half(c1[0] * inv);
        d_ap16[(size_t)b * DN + tp + 24] = __float2half(c1[2] * inv);
    }
}

// ---------------- stage D: gh pre-computed in barrier window ----------------
__device__ __forceinline__ void stageD_gh(const __half* __restrict__ h16to,
                                          const __half* wIH_s, float cH[3][4]) {
    const int c = blockIdx.x;
    const int warp = threadIdx.x >> 5;
    const int mtl = warp >> 2, kh = warp & 3;
    const int bt = (c & 1) * 4 + mtl;
    const int kt0 = kh * 8;
    #pragma unroll
    for (int kt = 0; kt < 8; ++kt) {
        uint32_t Ah[4], Bf[2];
        ldAt(h16to, bt, kt0 + kt, Ah);
        const int k = (kt0 + kt) * 16;
        #pragma unroll
        for (int gate = 0; gate < 3; ++gate) {
            ldBs(wIH_s, DKP, (3 + gate) * 8, k, Bf);
            mma16816(cH[gate], Ah[0], Ah[1], Ah[2], Ah[3], Bf[0], Bf[1]);
        }
    }
}

__device__ __forceinline__ void stageD_rest(
    const __half* __restrict__ g16t,
    __half* __restrict__ h16n, __half* __restrict__ h16tn,
    const __half* wIH_s, const float* __restrict__ b_ih, const float* __restrict__ b_hh,
    float hreg[4], float cH[3][4], char* Rbase)
{
    const int c = blockIdx.x, tid = threadIdx.x;
    const int warp = tid >> 5, lane = tid & 31;
    const int jt = c >> 1;
    const int j0 = jt * 8;
    const int mtl = warp >> 2, kh = warp & 3;
    const int bt = (c & 1) * 4 + mtl;
    const int b0 = bt * 16;
    const int kt0 = kh * 8;
    float cI[3][4] = {};
    #pragma unroll
    for (int kt = 0; kt < 8; ++kt) {
        uint32_t Ag[4], Bf[2];
        ldAt(g16t, bt, kt0 + kt, Ag);
        const int k = (kt0 + kt) * 16;
        #pragma unroll
        for (int gate = 0; gate < 3; ++gate) {
            ldBs(wIH_s, DKP, gate * 8, k, Bf);
            mma16816(cI[gate], Ag[0], Ag[1], Ag[2], Ag[3], Bf[0], Bf[1]);
        }
    }
    float* s_part = (float*)Rbase;                  // 12 x 768 floats
    if (kh) {
        float* p = s_part + ((kh - 1) * 4 + mtl) * 768 + lane * 24;
        #pragma unroll
        for (int gg = 0; gg < 3; ++gg)
            #pragma unroll
            for (int i = 0; i < 4; ++i) { p[gg * 4 + i] = cI[gg][i]; p[12 + gg * 4 + i] = cH[gg][i]; }
    }
    __syncthreads();
    if (!kh) {
        #pragma unroll
        for (int q = 0; q < 3; ++q) {
            const float* p = s_part + (q * 4 + mtl) * 768 + lane * 24;
            #pragma unroll
            for (int gg = 0; gg < 3; ++gg)
                #pragma unroll
                for (int i = 0; i < 4; ++i) { cI[gg][i] += p[gg * 4 + i]; cH[gg][i] += p[12 + gg * 4 + i]; }
        }
        const int g = lane >> 2, tig = lane & 3;
        float hv[2][2];
        #pragma unroll
        for (int hi = 0; hi < 2; ++hi) {
            const int b = b0 + g + hi * 8;
            #pragma unroll
            for (int ccx = 0; ccx < 2; ++ccx) {
                const int j = j0 + tig * 2 + ccx;
                const int ri = hi * 2 + ccx;
                float ir  = cI[0][ri] + b_ih[j];
                float iz  = cI[1][ri] + b_ih[DN + j];
                float in_ = cI[2][ri] + b_ih[2 * DN + j];
                float hr  = cH[0][ri] + b_hh[j];
                float hz  = cH[1][ri] + b_hh[DN + j];
                float hn  = cH[2][ri] + b_hh[2 * DN + j];
                float r = 1.0f / (1.0f + __expf(-(ir + hr)));
                float z = 1.0f / (1.0f + __expf(-(iz + hz)));
                float n = tanhf(in_ + r * hn);
                float hold = hreg[ri];
                float hnew = (1.0f - z) * n + z * hold;
                hreg[ri] = hnew;
                hv[hi][ccx] = hnew;
            }
            *(__half2*)(h16n + (size_t)b * DN + j0 + tig * 2)
                = __floats2half2_rn(hv[hi][0], hv[hi][1]);
        }
        {
            const int kt = jt >> 1;
            __half2 h0 = __floats2half2_rn(hv[0][0], hv[0][1]);
            __half2 h1 = __floats2half2_rn(hv[1][0], hv[1][1]);
            uint2 u;
            u.x = *(uint32_t*)&h0;
            u.y = *(uint32_t*)&h1;
            *(uint2*)(h16tn + ((size_t)(bt * 32 + kt) << 8) + lane * 8 + (jt & 1) * 4) = u;
        }
    }
}

// ---------------- final out GEMM ----------------
__device__ __forceinline__ void gemm_out(
    const __half* __restrict__ h16, const float* __restrict__ out_b,
    float* __restrict__ out, char* Rbase)
{
    const int c = blockIdx.x, tid = threadIdx.x;
    const int warp = tid >> 5, lane = tid & 31;
    const int b0 = (c >> 4) * 16, ng = c & 15;
    const int nt = warp & 3, kh = warp >> 2;
    __half* s_tile = (__half*)Rbase;
    float*  s_part = (float*)(Rbase + 16640);
    #pragma unroll
    for (int i = 0; i < 2; ++i) {
        int u = tid + i * NTHR;
        int row = u >> 6, c16 = u & 63;
        *(uint4*)(s_tile + row * DKP + c16 * 8)
            = *(const uint4*)(h16 + (size_t)(b0 + row) * DN + c16 * 8);
    }
    __syncthreads();
    float cc[4] = {0.f, 0.f, 0.f, 0.f};
    const int k0 = kh * 128;
    #pragma unroll
    for (int k = 0; k < 128; k += 16) {
        uint32_t A[4], Bf[2];
        ldAs(s_tile, DKP, k0 + k, A);
        ldB(d_wO, DN, ng * 32 + nt * 8, k0 + k, Bf);
        mma16816(cc, A[0], A[1], A[2], A[3], Bf[0], Bf[1]);
    }
    if (kh) {
        float* p = s_part + ((kh - 1) * 4 + nt) * 128 + lane * 4;
        p[0] = cc[0]; p[1] = cc[1]; p[2] = cc[2]; p[3] = cc[3];
    }
    __syncthreads();
    if (!kh) {
        #pragma unroll
        for (int q = 0; q < 3; ++q) {
            const float* p = s_part + (q * 4 + nt) * 128 + lane * 4;
            cc[0] += p[0]; cc[1] += p[1]; cc[2] += p[2]; cc[3] += p[3];
        }
        const int g = lane >> 2, tig = lane & 3;
        const int j = ng * 32 + nt * 8 + tig * 2;
        const float bz0 = out_b[j], bz1 = out_b[j + 1];
        *(float2*)(out + (size_t)(b0 + g) * DN + j)     = make_float2(cc[0] + bz0, cc[1] + bz1);
        *(float2*)(out + (size_t)(b0 + g + 8) * DN + j) = make_float2(cc[2] + bz0, cc[3] + bz1);
    }
}

// ---------------- persistent kernel ----------------
__global__ void __launch_bounds__(NTHR, 1) rnn_mma(
    const float* __restrict__ attn_b, const float* __restrict__ comb_b,
    const float* __restrict__ b_ih, const float* __restrict__ b_hh,
    const float* __restrict__ out_b, float* __restrict__ out)
{
    extern __shared__ char smem[];
    __half* wA_s  = (__half*)(smem + OFF_WA);    // h-half of attn_W (32j x 512k)
    __half* wC_s  = (__half*)(smem + OFF_WC);    // ap-half of comb_W
    __half* wIH_s = (__half*)(smem + OFF_WIH);
    char*   Rbase = smem + OFF_R;
    __half* s_tile = (__half*)Rbase;

    const int c = blockIdx.x, tid = threadIdx.x;
    const int b0AC = (c >> 4) * 16;

    // ---- one-time weight preload into smem ----
    {
        const int j0AC = (c & 15) * 32;
        #pragma unroll
        for (int i = 0; i < 4; ++i) {
            int u = tid + i * NTHR;          // 0..2047: 32 rows x 64 uint4
            int row = u >> 6, cc = u & 63;
            *(uint4*)(wA_s + row * DKP + cc * 8)
                = *(const uint4*)(d_wA + (size_t)(j0AC + row) * (2 * DN) + 512 + cc * 8);
            *(uint4*)(wC_s + row * DKP + cc * 8)
                = *(const uint4*)(d_wC + (size_t)(j0AC + row) * (2 * DN) + 512 + cc * 8);
        }
        const int j0D = (c >> 1) * 8;
        #pragma unroll
        for (int i = 0; i < 6; ++i) {
            int u = tid + i * NTHR;
            int row = u >> 6, c16 = u & 63;
            int mat = row / 24, rem = row % 24;
            int gate = rem >> 3, jr = rem & 7;
            const __half* src = (mat ? d_wH : d_wI)
                + (size_t)(gate * DN + j0D + jr) * DN + c16 * 8;
            *(uint4*)(wIH_s + row * DKP + c16 * 8) = *(const uint4*)src;
        }
    }
    __syncthreads();

    float hreg[4] = {0.f, 0.f, 0.f, 0.f};
    unsigned ep = 0;

    for (int t = 0; t < TN; ++t) {
        // ---- stage A: h-half GEMM + precomputed LX partial ----
        load_k512(d_h16[t & 1], s_tile, b0AC);
        __syncthreads();
        mma_AC(wA_s, d_LX + (size_t)t * HSZ, attn_b, 0, nullptr, Rbase);
        bar_arrive(ep);
        // ---- stage B: tensor-core einsum (prefetch + wait inside) ----
        stageB(Rbase, ep);
        bar_arrive(ep);
        bar_wait(ep);
        // ---- stage C: ap-half GEMM + precomputed CX partial ----
        load_k512(d_ap16, s_tile, b0AC);
        __syncthreads();
        mma_AC(wC_s, d_CX + (size_t)t * HSZ, comb_b, 1, d_g16t, Rbase);
        bar_arrive(ep);
        // ---- stage D: gh-GEMM hoisted into the barrier window ----
        float cH[3][4] = {};
        stageD_gh(d_h16t[t & 1], wIH_s, cH);
        bar_wait(ep);
        stageD_rest(d_g16t, d_h16[(t + 1) & 1], d_h16t[(t + 1) & 1],
                    wIH_s, b_ih, b_hh, hreg, cH, Rbase);
        bar_arrive(ep);
        bar_wait(ep);
    }
    gemm_out(d_h16[0], out_b, out, Rbase);
}

// ---------------- launch ----------------
extern "C" void kernel_launch(void* const* d_in, const int* in_sizes, int n_in,
                              void* d_out, int out_size) {
    (void)in_sizes; (void)n_in; (void)out_size;
    const float* x      = (const float*)d_in[0];
    const float* attn_W = (const float*)d_in[1];
    const float* attn_b = (const float*)d_in[2];
    const float* comb_W = (const float*)d_in[3];
    const float* comb_b = (const float*)d_in[4];
    const float* w_ih   = (const float*)d_in[5];
    const float* w_hh   = (const float*)d_in[6];
    const float* b_ih   = (const float*)d_in[7];
    const float* b_hh   = (const float*)d_in[8];
    const float* out_W  = (const float*)d_in[9];
    const float* out_b  = (const float*)d_in[10];
    float* out = (float*)d_out;

    static bool attr_set = false;
    if (!attr_set) {
        cudaFuncSetAttribute(rnn_mma, cudaFuncAttributeMaxDynamicSharedMemorySize,
                             SMEM_TOTAL);
        attr_set = true;
    }

    k_prep<<<36096, 256>>>(x, attn_W, comb_W, w_ih, w_hh, out_W);
    k_lxcx<<<dim3(512, 4, 2), 512>>>();
    rnn_mma<<<NCTA, NTHR, SMEM_TOTAL>>>(attn_b, comb_b, b_ih, b_hh, out_b, out);
}

// round 16
// speedup vs baseline: 1.0893x; 1.0893x over previous
#include <cuda_runtime.h>
#include <cuda_fp16.h>
#include <cstdint>

#define BN   128
#define DN   512
#define TN   512
#define NCTA 128
#define NTHR 512
#define HSZ  (BN * DN)   // 65536
#define HCTA 64          // CTAs per independent half

// padded smem row strides (halves)
#define DN2P 1032   // 1024-wide rows
#define DKP  520    // 512-wide rows

// dynamic smem byte offsets
#define OFF_WA   0                       // 32 x 1032 halves = 66048 B
#define OFF_WC   66048                   // 66048 B
#define OFF_WIH  132096                  // 48 x 520 halves  = 49920 B
#define OFF_R    182016                  // scratch union    = 43072 B
#define SMEM_TOTAL 225088

// Rbase internal layout:
//   s_tile  : 0      .. 33024   (A/C activation tile, 16 x 1032 halves)
//   s_part  : 33024  .. 39168   (A/C reduction partials)
//   s_e     : 39168  .. 40192   (stage B weights — OUTSIDE s_tile: xin persists A->C)
//   s_scr   : 40192  .. 40256
//   stage D s_part: 0 .. 36864  (clobbers s_tile; xin reloaded in D->A window)

// ---------------- device scratch ----------------
__device__ __align__(16) __half d_xe[(size_t)BN * 32 * 32 * 256]; // x^T frag-tiled (einsum A)
__device__ __align__(16) __half d_xbm[(size_t)TN * BN * DN];      // [t][b][m] GEMM A operand
__device__ __align__(16) __half d_wA[DN * 2 * DN];
__device__ __align__(16) __half d_wC[DN * 2 * DN];
__device__ __align__(16) __half d_wI[3 * DN * DN];
__device__ __align__(16) __half d_wH[3 * DN * DN];
__device__ __align__(16) __half d_wO[DN * DN];
__device__ __align__(16) float  d_elog[HSZ];                   // exp(logit) [b][j]
__device__ __align__(16) float  d_Spart[BN * 64];              // per-(b, jg*4+nt) partial sums
__device__ __align__(16) __half d_g16t[HSZ];                   // g, TILED frag layout
__device__ __align__(16) __half d_ap16[HSZ];                   // [b][t']
__device__ __align__(16) __half d_h16[2][HSZ];                 // h row-major [b][j]
__device__ __align__(16) __half d_h16t[2][HSZ];                // h TILED frag layout
__device__ unsigned d_cnt2[2 * 32];                            // per-half counters (128B apart)
__device__ unsigned d_sense2[2 * 32];                          // per-half sense words

// ---------------- merged prep kernel (identical to R13 + barrier init) ----------
__global__ void k_prep(const float* __restrict__ x,
                       const float* __restrict__ aW, const float* __restrict__ cW,
                       const float* __restrict__ wi, const float* __restrict__ wh,
                       const float* __restrict__ oW) {
    const int bx = blockIdx.x, tid = threadIdx.x;
    if (bx < 32768) {
        __shared__ float tile[32][33];
        int m0 = (bx & 15) * 32;
        int t0 = ((bx >> 4) & 15) * 32;
        int b  = bx >> 8;
        int tx = tid & 31;
        int ty = tid >> 5;
        #pragma unroll
        for (int r = 0; r < 32; r += 8)
            tile[ty + r][tx] = x[(size_t)b * DN * TN + (size_t)(m0 + ty + r) * TN + (t0 + tx)];
        __syncthreads();
        #pragma unroll
        for (int r = 0; r < 32; r += 8)
            d_xbm[(size_t)(t0 + ty + r) * HSZ + (size_t)b * DN + (m0 + tx)]
                = __float2half(tile[tx][ty + r]);
        {
            int sub = tid >> 6, v = tid & 63;
            int st = sub & 1, sm = sub >> 1;
            int L = v >> 1, p = v & 1;
            int g = L >> 2, tq = L & 3;
            int mb = sm * 16 + p * 8 + 2 * tq;
            int tb = st * 16 + g;
            __half2 h0 = __floats2half2_rn(tile[mb][tb],     tile[mb + 1][tb]);
            __half2 h1 = __floats2half2_rn(tile[mb][tb + 8], tile[mb + 1][tb + 8]);
            uint2 u;
            u.x = *(uint32_t*)&h0;
            u.y = *(uint32_t*)&h1;
            size_t base = (((size_t)b * 32 + (t0 >> 4) + st) * 32 + (m0 >> 4) + sm) * 256;
            *(uint2*)(d_xe + base + L * 8 + p * 4) = u;
        }
    } else if (bx < 35840) {
        int i = (bx - 32768) * 256 + tid;
        if (i < DN * 2 * DN) { d_wA[i] = __float2half(aW[i]); d_wC[i] = __float2half(cW[i]); }
        d_wI[i] = __float2half(wi[i]);
        d_wH[i] = __float2half(wh[i]);
        if (i < DN * DN) d_wO[i] = __float2half(oW[i]);
    } else {
        int i = (bx - 35840) * 256 + tid;
        if (i < HSZ) {
            d_h16[0][i]  = __float2half(0.0f);
            d_h16t[0][i] = __float2half(0.0f);
        }
        if (i < 2 * 32) { d_cnt2[i] = 0u; d_sense2[i] = 0u; }
    }
}

// ---------------- per-half flat barrier (64 CTAs; R7/R13 mechanism) ----------
__device__ __forceinline__ void bar_arrive(unsigned& ep, int gh) {
    __syncthreads();            // join CTA warps; protects smem reuse
    ep += HCTA;
    if (threadIdx.x == 0) {
        __threadfence();
        unsigned a = atomicAdd(&d_cnt2[gh * 32], 1u) + 1u;
        if (a == ep) atomicExch(&d_sense2[gh * 32], ep);
    }
}
__device__ __forceinline__ void bar_wait(unsigned ep, int gh) {
    if (threadIdx.x == 0) {
        while (*(volatile unsigned*)&d_sense2[gh * 32] < ep) { }
        __threadfence();
    }
    __syncthreads();
}

// ---------------- warp reduction ----------------
__device__ __forceinline__ float warpSum(float v) {
    #pragma unroll
    for (int o = 16; o; o >>= 1) v += __shfl_xor_sync(0xffffffffu, v, o);
    return v;
}

// ---------------- mma helpers ----------------
__device__ __forceinline__ void mma16816(float c[4], uint32_t a0, uint32_t a1,
                                         uint32_t a2, uint32_t a3,
                                         uint32_t b0, uint32_t b1) {
    asm volatile(
        "mma.sync.aligned.m16n8k16.row.col.f32.f16.f16.f32 "
        "{%0,%1,%2,%3}, {%4,%5,%6,%7}, {%8,%9}, {%0,%1,%2,%3};"
        : "+f"(c[0]), "+f"(c[1]), "+f"(c[2]), "+f"(c[3])
        : "r"(a0), "r"(a1), "r"(a2), "r"(a3), "r"(b0), "r"(b1));
}

__device__ __forceinline__ void ldAt(const __half* __restrict__ base, int bt, int kt,
                                     uint32_t A[4]) {
    const int lane = threadIdx.x & 31;
    uint4 v = *(const uint4*)(base + ((size_t)(bt * 32 + kt) << 8) + lane * 8);
    A[0] = v.x; A[1] = v.y; A[2] = v.z; A[3] = v.w;
}

__device__ __forceinline__ void ldB(const __half* __restrict__ W, int stride, int j0, int k,
                                    uint32_t Bf[2]) {
    const int lane = threadIdx.x & 31;
    const int g = lane >> 2, tig = lane & 3;
    const __half* p = W + (size_t)(j0 + g) * stride + k + tig * 2;
    Bf[0] = *(const uint32_t*)p;
    Bf[1] = *(const uint32_t*)(p + 8);
}

__device__ __forceinline__ void ldAs(const __half* s, int stridep, int k, uint32_t A[4]) {
    const int lane = threadIdx.x & 31;
    const int g = lane >> 2, tig = lane & 3;
    const __half* p0 = s + g * stridep + k + tig * 2;
    const __half* p1 = p0 + 8 * stridep;
    A[0] = *(const uint32_t*)p0;
    A[1] = *(const uint32_t*)p1;
    A[2] = *(const uint32_t*)(p0 + 8);
    A[3] = *(const uint32_t*)(p1 + 8);
}

__device__ __forceinline__ void ldBs(const __half* s, int stridep, int row0, int k,
                                     uint32_t Bf[2]) {
    const int lane = threadIdx.x & 31;
    const int g = lane >> 2, tig = lane & 3;
    const __half* p = s + (row0 + g) * stridep + k + tig * 2;
    Bf[0] = *(const uint32_t*)p;
    Bf[1] = *(const uint32_t*)(p + 8);
}

// ---------------- half-tile loader (all 512 threads) ----------------
__device__ __forceinline__ void load_half(const __half* __restrict__ src, __half* s_tile,
                                          int b0, int halfsel) {
    const int tid = threadIdx.x;
    #pragma unroll
    for (int i = 0; i < 2; ++i) {
        int u = tid + i * NTHR;
        int row = u >> 6, cc = u & 63;
        *(uint4*)(s_tile + row * DN2P + (halfsel * 64 + cc) * 8)
            = *(const uint4*)(src + (size_t)(b0 + row) * DN + cc * 8);
    }
}

// ---------------- stages A / C compute (tile already in smem) ----------------
// CTA (half gh, local lc): b0 = gh*64 + (lc>>4)*16, ng = lc&15.
// mode 0: exp epilogue -> d_elog + d_Spart. mode 1: relu -> TILED fp16 g16t.
__device__ __forceinline__ void mma_AC(
    const __half* wS, const float* __restrict__ bias, int mode,
    __half* __restrict__ out16t, char* Rbase, int gh, int lc)
{
    const int tid = threadIdx.x;
    const int warp = tid >> 5, lane = tid & 31;
    const int b0 = gh * 64 + (lc >> 4) * 16, ng = lc & 15;
    const int nt = warp & 3, kh = warp >> 2;
    __half* s_tile = (__half*)Rbase;
    float*  s_part = (float*)(Rbase + 33024);

    float cc[4] = {0.f, 0.f, 0.f, 0.f};
    const int k0 = kh * 256;
    #pragma unroll 4
    for (int k = 0; k < 256; k += 16) {
        uint32_t A[4], Bf[2];
        ldAs(s_tile, DN2P, k0 + k, A);
        ldBs(wS, DN2P, nt * 8, k0 + k, Bf);
        mma16816(cc, A[0], A[1], A[2], A[3], Bf[0], Bf[1]);
    }
    if (kh) {
        float* p = s_part + ((kh - 1) * 4 + nt) * 128 + lane * 4;
        p[0] = cc[0]; p[1] = cc[1]; p[2] = cc[2]; p[3] = cc[3];
    }
    __syncthreads();
    if (!kh) {
        #pragma unroll
        for (int q = 0; q < 3; ++q) {
            const float* p = s_part + (q * 4 + nt) * 128 + lane * 4;
            cc[0] += p[0]; cc[1] += p[1]; cc[2] += p[2]; cc[3] += p[3];
        }
        const int g = lane >> 2, tig = lane & 3;
        const int j = ng * 32 + nt * 8 + tig * 2;
        const float bz0 = bias[j], bz1 = bias[j + 1];
        if (mode == 1) {
            float v0 = fmaxf(cc[0] + bz0, 0.f), v1 = fmaxf(cc[1] + bz1, 0.f);
            float v2 = fmaxf(cc[2] + bz0, 0.f), v3 = fmaxf(cc[3] + bz1, 0.f);
            const int kt = ng * 2 + (nt >> 1);
            __half2 h0 = __floats2half2_rn(v0, v1);
            __half2 h1 = __floats2half2_rn(v2, v3);
            uint2 u;
            u.x = *(uint32_t*)&h0;
            u.y = *(uint32_t*)&h1;
            *(uint2*)(out16t + ((size_t)((b0 >> 4) * 32 + kt) << 8) + lane * 8 + (nt & 1) * 4) = u;
        } else {
            float e0 = __expf(cc[0] + bz0), e1 = __expf(cc[1] + bz1);
            float e2 = __expf(cc[2] + bz0), e3 = __expf(cc[3] + bz1);
            *(float2*)(d_elog + (size_t)(b0 + g) * DN + j)     = make_float2(e0, e1);
            *(float2*)(d_elog + (size_t)(b0 + g + 8) * DN + j) = make_float2(e2, e3);
            float s01 = e0 + e1, s23 = e2 + e3;
            s01 += __shfl_xor_sync(0xffffffffu, s01, 1);
            s23 += __shfl_xor_sync(0xffffffffu, s23, 1);
            s01 += __shfl_xor_sync(0xffffffffu, s01, 2);
            s23 += __shfl_xor_sync(0xffffffffu, s23, 2);
            if (tig == 0) {
                d_Spart[(b0 + g) * 64 + ng * 4 + nt]     = s01;
                d_Spart[(b0 + g + 8) * 64 + ng * 4 + nt] = s23;
            }
        }
    }
}

// ---------------- stage B: tensor-core einsum, CTA c = batch c (R13-proven) ----
__device__ __forceinline__ void stageB(char* Rbase, unsigned ep, int gh) {
    const int b = blockIdx.x, tid = threadIdx.x;   // batch == global CTA id
    const int warp = tid >> 5, lane = tid & 31;
    const int g = lane >> 2, tq = lane & 3;
    __half* s_e   = (__half*)(Rbase + 39168);    // outside s_tile: xin persists
    float*  s_scr = (float*)(Rbase + 40192);
    const __half* xb = d_xe + ((size_t)b * 32 + warp * 2) * 32 * 256;

    // prefetch first 4 k-tiles of both M-tiles (no barrier dependency)
    uint4 p0[4], p1[4];
    #pragma unroll
    for (int i = 0; i < 4; ++i) {
        p0[i] = *(const uint4*)(xb + (size_t)i * 256 + lane * 8);
        p1[i] = *(const uint4*)(xb + (size_t)(32 + i) * 256 + lane * 8);
    }

    bar_wait(ep, gh);   // logits/Spart for this half now visible

    float part = d_Spart[b * 64 + (tid & 63)];
    s_e[tid] = __float2half(d_elog[(size_t)b * DN + tid]);
    float ws = warpSum(part);
    if (lane == 0) s_scr[warp] = ws;
    __syncthreads();
    const float inv = 1.0f / (s_scr[0] + s_scr[1]);

    float c0[4] = {0.f, 0.f, 0.f, 0.f};
    float c1[4] = {0.f, 0.f, 0.f, 0.f};
    #pragma unroll
    for (int k = 0; k < 4; ++k) {
        uint32_t e0 = *(const uint32_t*)(s_e + k * 16 + 2 * tq);
        uint32_t e1 = *(const uint32_t*)(s_e + k * 16 + 8 + 2 * tq);
        mma16816(c0, p0[k].x, p0[k].y, p0[k].z, p0[k].w, e0, e1);
        mma16816(c1, p1[k].x, p1[k].y, p1[k].z, p1[k].w, e0, e1);
    }
    #pragma unroll
    for (int k = 4; k < 32; ++k) {
        uint4 v0 = *(const uint4*)(xb + (size_t)k * 256 + lane * 8);
        uint4 v1 = *(const uint4*)(xb + (size_t)(32 + k) * 256 + lane * 8);
        uint32_t e0 = *(const uint32_t*)(s_e + k * 16 + 2 * tq);
        uint32_t e1 = *(const uint32_t*)(s_e + k * 16 + 8 + 2 * tq);
        mma16816(c0, v0.x, v0.y, v0.z, v0.w, e0, e1);
        mma16816(c1, v1.x, v1.y, v1.z, v1.w, e0, e1);
    }
    if (tq == 0) {
        int tp = warp * 32 + g;
        d_ap16[(size_t)b * DN + tp]      = __float2half(c0[0] * inv);
        d_ap16[(size_t)b * DN + tp + 8]  = __float2half(c0[2] * inv);
        d_ap16[(size_t)b * DN + tp + 16] = __float2half(c1[0] * inv);
        d_ap16[(size_t)b * DN + tp + 24] = __float2half(c1[2] * inv);
    }
}

// ---------------- stage D: gh-GEMM pre-computed in barrier window ----------------
// CTA (gh, lc): jt = lc (j0 = lc*8); warps: mtl = warp>>2, kh = warp&3;
// bt = gh*4 + mtl (4 b-tiles of this half).
__device__ __forceinline__ void stageD_gh(const __half* __restrict__ h16to,
                                          const __half* wIH_s, float cH[3][4],
                                          int gh) {
    const int warp = threadIdx.x >> 5;
    const int mtl = warp >> 2, kh = warp & 3;
    const int bt = gh * 4 + mtl;
    const int kt0 = kh * 8;
    #pragma unroll
    for (int kt = 0; kt < 8; ++kt) {
        uint32_t Ah[4], Bf[2];
        ldAt(h16to, bt, kt0 + kt, Ah);
        const int k = (kt0 + kt) * 16;
        #pragma unroll
        for (int gate = 0; gate < 3; ++gate) {
            ldBs(wIH_s, DKP, (3 + gate) * 8, k, Bf);
            mma16816(cH[gate], Ah[0], Ah[1], Ah[2], Ah[3], Bf[0], Bf[1]);
        }
    }
}

__device__ __forceinline__ void stageD_rest(
    const __half* __restrict__ g16t,
    __half* __restrict__ h16n, __half* __restrict__ h16tn,
    const __half* wIH_s, const float* __restrict__ b_ih, const float* __restrict__ b_hh,
    float hreg[4], float cH[3][4], char* Rbase, int gh, int lc)
{
    const int tid = threadIdx.x;
    const int warp = tid >> 5, lane = tid & 31;
    const int jt = lc;
    const int j0 = jt * 8;
    const int mtl = warp >> 2, kh = warp & 3;
    const int bt = gh * 4 + mtl;
    const int b0 = bt * 16;
    const int kt0 = kh * 8;
    float cI[3][4] = {};
    #pragma unroll
    for (int kt = 0; kt < 8; ++kt) {
        uint32_t Ag[4], Bf[2];
        ldAt(g16t, bt, kt0 + kt, Ag);
        const int k = (kt0 + kt) * 16;
        #pragma unroll
        for (int gate = 0; gate < 3; ++gate) {
            ldBs(wIH_s, DKP, gate * 8, k, Bf);
            mma16816(cI[gate], Ag[0], Ag[1], Ag[2], Ag[3], Bf[0], Bf[1]);
        }
    }
    float* s_part = (float*)Rbase;                  // 12 x 768 floats
    if (kh) {
        float* p = s_part + ((kh - 1) * 4 + mtl) * 768 + lane * 24;
        #pragma unroll
        for (int gg = 0; gg < 3; ++gg)
            #pragma unroll
            for (int i = 0; i < 4; ++i) { p[gg * 4 + i] = cI[gg][i]; p[12 + gg * 4 + i] = cH[gg][i]; }
    }
    __syncthreads();
    if (!kh) {
        #pragma unroll
        for (int q = 0; q < 3; ++q) {
            const float* p = s_part + (q * 4 + mtl) * 768 + lane * 24;
            #pragma unroll
            for (int gg = 0; gg < 3; ++gg)
                #pragma unroll
                for (int i = 0; i < 4; ++i) { cI[gg][i] += p[gg * 4 + i]; cH[gg][i] += p[12 + gg * 4 + i]; }
        }
        const int g = lane >> 2, tig = lane & 3;
        float hv[2][2];
        #pragma unroll
        for (int hi = 0; hi < 2; ++hi) {
            const int b = b0 + g + hi * 8;
            #pragma unroll
            for (int ccx = 0; ccx < 2; ++ccx) {
                const int j = j0 + tig * 2 + ccx;
                const int ri = hi * 2 + ccx;
                float ir  = cI[0][ri] + b_ih[j];
                float iz  = cI[1][ri] + b_ih[DN + j];
                float in_ = cI[2][ri] + b_ih[2 * DN + j];
                float hr  = cH[0][ri] + b_hh[j];
                float hz  = cH[1][ri] + b_hh[DN + j];
                float hn  = cH[2][ri] + b_hh[2 * DN + j];
                float r = 1.0f / (1.0f + __expf(-(ir + hr)));
                float z = 1.0f / (1.0f + __expf(-(iz + hz)));
                float n = tanhf(in_ + r * hn);
                float hold = hreg[ri];
                float hnew = (1.0f - z) * n + z * hold;
                hreg[ri] = hnew;
                hv[hi][ccx] = hnew;
            }
            *(__half2*)(h16n + (size_t)b * DN + j0 + tig * 2)
                = __floats2half2_rn(hv[hi][0], hv[hi][1]);
        }
        {
            const int kt = jt >> 1;
            __half2 h0 = __floats2half2_rn(hv[0][0], hv[0][1]);
            __half2 h1 = __floats2half2_rn(hv[1][0], hv[1][1]);
            uint2 u;
            u.x = *(uint32_t*)&h0;
            u.y = *(uint32_t*)&h1;
            *(uint2*)(h16tn + ((size_t)(bt * 32 + kt) << 8) + lane * 8 + (jt & 1) * 4) = u;
        }
    }
}

// ---------------- final out GEMM ----------------
__device__ __forceinline__ void gemm_out(
    const __half* __restrict__ h16, const float* __restrict__ out_b,
    float* __restrict__ out, char* Rbase, int gh, int lc)
{
    const int tid = threadIdx.x;
    const int warp = tid >> 5, lane = tid & 31;
    const int b0 = gh * 64 + (lc >> 4) * 16, ng = lc & 15;
    const int nt = warp & 3, kh = warp >> 2;
    __half* s_tile = (__half*)Rbase;
    float*  s_part = (float*)(Rbase + 16640);
    #pragma unroll
    for (int i = 0; i < 2; ++i) {
        int u = tid + i * NTHR;
        int row = u >> 6, c16 = u & 63;
        *(uint4*)(s_tile + row * DKP + c16 * 8)
            = *(const uint4*)(h16 + (size_t)(b0 + row) * DN + c16 * 8);
    }
    __syncthreads();
    float cc[4] = {0.f, 0.f, 0.f, 0.f};
    const int k0 = kh * 128;
    #pragma unroll
    for (int k = 0; k < 128; k += 16) {
        uint32_t A[4], Bf[2];
        ldAs(s_tile, DKP, k0 + k, A);
        ldB(d_wO, DN, ng * 32 + nt * 8, k0 + k, Bf);
        mma16816(cc, A[0], A[1], A[2], A[3], Bf[0], Bf[1]);
    }
    if (kh) {
        float* p = s_part + ((kh - 1) * 4 + nt) * 128 + lane * 4;
        p[0] = cc[0]; p[1] = cc[1]; p[2] = cc[2]; p[3] = cc[3];
    }
    __syncthreads();
    if (!kh) {
        #pragma unroll
        for (int q = 0; q < 3; ++q) {
            const float* p = s_part + (q * 4 + nt) * 128 + lane * 4;
            cc[0] += p[0]; cc[1] += p[1]; cc[2] += p[2]; cc[3] += p[3];
        }
        const int g = lane >> 2, tig = lane & 3;
        const int j = ng * 32 + nt * 8 + tig * 2;
        const float bz0 = out_b[j], bz1 = out_b[j + 1];
        *(float2*)(out + (size_t)(b0 + g) * DN + j)     = make_float2(cc[0] + bz0, cc[1] + bz1);
        *(float2*)(out + (size_t)(b0 + g + 8) * DN + j) = make_float2(cc[2] + bz0, cc[3] + bz1);
    }
}

// ---------------- persistent kernel ----------------
__global__ void __launch_bounds__(NTHR, 1) rnn_mma(
    const float* __restrict__ attn_b, const float* __restrict__ comb_b,
    const float* __restrict__ b_ih, const float* __restrict__ b_hh,
    const float* __restrict__ out_b, float* __restrict__ out)
{
    extern __shared__ char smem[];
    __half* wA_s  = (__half*)(smem + OFF_WA);
    __half* wC_s  = (__half*)(smem + OFF_WC);
    __half* wIH_s = (__half*)(smem + OFF_WIH);
    char*   Rbase = smem + OFF_R;
    __half* s_tile = (__half*)Rbase;

    const int c = blockIdx.x, tid = threadIdx.x;
    const int gh = c >> 6;            // independent half 0/1 (batches gh*64..+63)
    const int lc = c & 63;            // local CTA id within half
    const int b0AC = gh * 64 + (lc >> 4) * 16;

    // ---- one-time weight preload into smem ----
    {
        const int j0AC = (lc & 15) * 32;
        #pragma unroll
        for (int i = 0; i < 8; ++i) {
            int u = tid + i * NTHR;
            int row = u >> 7, c16 = u & 127;
            *(uint4*)(wA_s + row * DN2P + c16 * 8)
                = *(const uint4*)(d_wA + (size_t)(j0AC + row) * (2 * DN) + c16 * 8);
            *(uint4*)(wC_s + row * DN2P + c16 * 8)
                = *(const uint4*)(d_wC + (size_t)(j0AC + row) * (2 * DN) + c16 * 8);
        }
        const int j0D = lc * 8;
        #pragma unroll
        for (int i = 0; i < 6; ++i) {
            int u = tid + i * NTHR;
            int row = u >> 6, c16 = u & 63;
            int mat = row / 24, rem = row % 24;
            int gate = rem >> 3, jr = rem & 7;
            const __half* src = (mat ? d_wH : d_wI)
                + (size_t)(gate * DN + j0D + jr) * DN + c16 * 8;
            *(uint4*)(wIH_s + row * DKP + c16 * 8) = *(const uint4*)src;
        }
    }
    __syncthreads();

    float hreg[4] = {0.f, 0.f, 0.f, 0.f};
    unsigned ep = 0;

    // prologue: xin tile for t=0
    load_half(d_xbm, s_tile, b0AC, 0);

    for (int t = 0; t < TN; ++t) {
        // ---- stage A (xin half persists/preloaded; h ready from D-barrier) ----
        load_half(d_h16[t & 1], s_tile, b0AC, 1);
        __syncthreads();
        mma_AC(wA_s, attn_b, 0, nullptr, Rbase, gh, lc);
        bar_arrive(ep, gh);
        // ---- stage B: tensor-core einsum (prefetch + wait inside) ----
        // touches only Rbase+39168.. — xin half of s_tile survives into stage C
        stageB(Rbase, ep, gh);
        bar_arrive(ep, gh);
        bar_wait(ep, gh);
        // ---- stage C (xin persists from A; load only the ap half) ----
        load_half(d_ap16, s_tile, b0AC, 1);
        __syncthreads();
        mma_AC(wC_s, comb_b, 1, d_g16t, Rbase, gh, lc);
        bar_arrive(ep, gh);
        // ---- stage D: gh-GEMM hoisted into the barrier window (h is stable) ----
        float cH[3][4] = {};
        stageD_gh(d_h16t[t & 1], wIH_s, cH, gh);
        bar_wait(ep, gh);
        stageD_rest(d_g16t, d_h16[(t + 1) & 1], d_h16t[(t + 1) & 1],
                    wIH_s, b_ih, b_hh, hreg, cH, Rbase, gh, lc);
        bar_arrive(ep, gh);
        if (t + 1 < TN)
            load_half(d_xbm + (size_t)(t + 1) * HSZ, s_tile, b0AC, 0);  // overlap
        bar_wait(ep, gh);
    }
    gemm_out(d_h16[0], out_b, out, Rbase, gh, lc);
}

// ---------------- launch ----------------
extern "C" void kernel_launch(void* const* d_in, const int* in_sizes, int n_in,
                              void* d_out, int out_size) {
    (void)in_sizes; (void)n_in; (void)out_size;
    const float* x      = (const float*)d_in[0];
    const float* attn_W = (const float*)d_in[1];
    const float* attn_b = (const float*)d_in[2];
    const float* comb_W = (const float*)d_in[3];
    const float* comb_b = (const float*)d_in[4];
    const float* w_ih   = (const float*)d_in[5];
    const float* w_hh   = (const float*)d_in[6];
    const float* b_ih   = (const float*)d_in[7];
    const float* b_hh   = (const float*)d_in[8];
    const float* out_W  = (const float*)d_in[9];
    const float* out_b  = (const float*)d_in[10];
    float* out = (float*)d_out;

    static bool attr_set = false;
    if (!attr_set) {
        cudaFuncSetAttribute(rnn_mma, cudaFuncAttributeMaxDynamicSharedMemorySize,
                             SMEM_TOTAL);
        attr_set = true;
    }

    k_prep<<<36096, 256>>>(x, attn_W, comb_W, w_ih, w_hh, out_W);
    rnn_mma<<<NCTA, NTHR, SMEM_TOTAL>>>(attn_b, comb_b, b_ih, b_hh, out_b, out);
}